// round 17
// baseline (speedup 1.0000x reference)
#include <cuda_runtime.h>
#include <math.h>

#define T_LEN 2048
#define NB    256
#define DMOD  64
#define H_OUT 720
#define NBINS 1024
#define NH    1024
#define OUTSPAN 928
#define USPAN  1024
#define XLEN2  1136
#define NCONVBLK 5
#define KSPLIT 4
#define KSEG  (T_LEN / KSPLIT)

typedef unsigned long long ull;

struct PMeta {
    int S, padL, inner, outer, stepO, stepI, orient;
    unsigned magic;
    float wgt;
};
__device__ PMeta g_pm[2];
__device__ float g_amp[NBINS];
__device__ float g_partial[NBINS * NB];
__device__ float2 g_wq[2][2][(DMOD/2) * 9];
__device__ float2 g_b1q[DMOD / 2];
__device__ float g_y2[2][NB * T_LEN];
__device__ float g_hp[KSPLIT][NB * H_OUT];

__device__ __forceinline__ unsigned mdiv(unsigned q, unsigned M) {
    return (unsigned)(((unsigned long long)q * M) >> 32);
}
__device__ __forceinline__ float2 cmul(float2 a, float2 b) {
    return make_float2(a.x * b.x - a.y * b.y, a.x * b.y + a.y * b.x);
}

// ---- f32x2 packed helpers ----
__device__ __forceinline__ ull pack2(float lo, float hi) {
    ull r; asm("mov.b64 %0, {%1, %2};" : "=l"(r) : "f"(lo), "f"(hi)); return r;
}
__device__ __forceinline__ ull bcast2(float v) { return pack2(v, v); }
__device__ __forceinline__ void unpack2(ull v, float& lo, float& hi) {
    asm("mov.b64 {%0, %1}, %2;" : "=f"(lo), "=f"(hi) : "l"(v));
}
__device__ __forceinline__ ull fma2(ull a, ull b, ull c) {
    ull d; asm("fma.rn.f32x2 %0, %1, %2, %3;" : "=l"(d) : "l"(a), "l"(b), "l"(c)); return d;
}
__device__ __forceinline__ ull mul2(ull a, ull b) {
    ull d; asm("mul.rn.f32x2 %0, %1, %2;" : "=l"(d) : "l"(a), "l"(b)); return d;
}

// ---------------------------------------------------------------------------
// 1) Real-input FFT: pack to 1024 complex, radix-2^2, conj-symmetry unpack
// ---------------------------------------------------------------------------
__global__ __launch_bounds__(512) void fft_kernel(const float* __restrict__ x) {
    __shared__ float2 s[NH];
    __shared__ float2 tw[NH / 2];
    int b = blockIdx.x, tid = threadIdx.x;
    const float* xb = x + (size_t)b * T_LEN;

    for (int i = tid; i < NH; i += 512) {
        int rev = __brev((unsigned)i) >> 22;
        const float2 v = *(const float2*)(xb + 2 * i);
        s[rev] = v;
    }
    const float base = -6.283185307179586f / (float)NH;
    if (tid < NH / 2) {
        float sa, ca;
        __sincosf(base * (float)tid, &sa, &ca);
        tw[tid] = make_float2(ca, sa);
    }
    __syncthreads();

    {
        int g = tid;
        float2 a = s[2 * g], c = s[2 * g + 1];
        s[2 * g]     = make_float2(a.x + c.x, a.y + c.y);
        s[2 * g + 1] = make_float2(a.x - c.x, a.y - c.y);
    }
    __syncthreads();

    #pragma unroll
    for (int m = 4; m <= 256; m *= 4) {
        if (tid < NH / 4) {
            int half = m >> 1;
            int tstep1 = NH / m;
            int tstep2 = NH / (2 * m);
            int gidx = tid;
            int blk = gidx / half;
            int j   = gidx - blk * half;
            int B   = blk * 2 * m;
            int p0 = B + j, p1 = p0 + half, p2 = p0 + m, p3 = p2 + half;
            float2 wA = tw[j * tstep1];
            float2 wB = tw[j * tstep2];
            float2 u0 = s[p0], u1 = s[p1], u2 = s[p2], u3 = s[p3];
            float2 t1 = cmul(wA, u1);
            float2 a0 = make_float2(u0.x + t1.x, u0.y + t1.y);
            float2 a1 = make_float2(u0.x - t1.x, u0.y - t1.y);
            float2 t3 = cmul(wA, u3);
            float2 a2 = make_float2(u2.x + t3.x, u2.y + t3.y);
            float2 a3 = make_float2(u2.x - t3.x, u2.y - t3.y);
            float2 t2 = cmul(wB, a2);
            float2 t4 = cmul(wB, a3);
            t4 = make_float2(t4.y, -t4.x);
            s[p0] = make_float2(a0.x + t2.x, a0.y + t2.y);
            s[p2] = make_float2(a0.x - t2.x, a0.y - t2.y);
            s[p1] = make_float2(a1.x + t4.x, a1.y + t4.y);
            s[p3] = make_float2(a1.x - t4.x, a1.y - t4.y);
        }
        __syncthreads();
    }

    {
        int j = tid;
        float2 w = tw[j];
        float2 u = s[j], v = s[j + NH / 2];
        float2 t = cmul(w, v);
        s[j]          = make_float2(u.x + t.x, u.y + t.y);
        s[j + NH / 2] = make_float2(u.x - t.x, u.y - t.y);
    }
    __syncthreads();

    const float ubase = -6.283185307179586f / (float)T_LEN;
    for (int k = 1 + tid; k < NH; k += 512) {
        float2 Zk = s[k];
        float2 Zm = s[NH - k];
        float2 A = make_float2(0.5f * (Zk.x + Zm.x), 0.5f * (Zk.y - Zm.y));
        float2 B = make_float2(0.5f * (Zk.y + Zm.y), -0.5f * (Zk.x - Zm.x));
        float sn, cs;
        __sincosf(ubase * (float)k, &sn, &cs);
        float Xr = A.x + cs * B.x - sn * B.y;
        float Xi = A.y + cs * B.y + sn * B.x;
        g_partial[(size_t)(k - 1) * NB + b] = sqrtf(Xr * Xr + Xi * Xi);
    }
    if (tid == 0) {
        float2 Z0 = s[0];
        g_partial[(size_t)(NH - 1) * NB + b] = fabsf(Z0.x - Z0.y);
    }
}

__global__ void reduce_amp_kernel() {
    int k = blockIdx.x * blockDim.x + threadIdx.x;
    if (k >= NBINS) return;
    const float4* p = (const float4*)&g_partial[(size_t)k * NB];
    float acc = 0.f;
    #pragma unroll 8
    for (int i = 0; i < NB / 4; i++) {
        float4 v = p[i];
        acc += v.x + v.y + v.z + v.w;
    }
    g_amp[k] = acc * (1.f / (float)NB);
}

// ---------------------------------------------------------------------------
// 2) prep: weight packs + single-pass top-2 + per-period meta (S = inner+2)
// ---------------------------------------------------------------------------
struct Top2 { float v1; int i1; float v2; int i2; };

__device__ __forceinline__ bool t2gt(float av, int ai, float bv, int bi) {
    return av > bv || (av == bv && ai < bi);
}
__device__ __forceinline__ Top2 t2merge(Top2 a, Top2 b) {
    Top2 r;
    if (t2gt(a.v1, a.i1, b.v1, b.i1)) {
        r.v1 = a.v1; r.i1 = a.i1;
        if (t2gt(a.v2, a.i2, b.v1, b.i1)) { r.v2 = a.v2; r.i2 = a.i2; }
        else                              { r.v2 = b.v1; r.i2 = b.i1; }
    } else {
        r.v1 = b.v1; r.i1 = b.i1;
        if (t2gt(b.v2, b.i2, a.v1, a.i1)) { r.v2 = b.v2; r.i2 = b.i2; }
        else                              { r.v2 = a.v1; r.i2 = a.i1; }
    }
    return r;
}

__global__ void prep_kernel(const float* __restrict__ w1,
                            const float* __restrict__ w2,
                            const float* __restrict__ b1) {
    __shared__ Top2 warpRes[32];
    int tid = threadIdx.x;   // 1024

    const int NP = DMOD / 2;
    for (int idx = tid; idx < 2 * 2 * NP * 9; idx += 1024) {
        int orient = idx / (2 * NP * 9);
        int rem    = idx - orient * 2 * NP * 9;
        int layer  = rem / (NP * 9);
        int i      = rem - layer * NP * 9;
        int p = i / 9, s = i - p * 9;
        int g = s / 3, di = s % 3 - 1;
        int do_ = (g == 0) ? 0 : (g == 1 ? 1 : -1);
        int off = orient ? ((do_ + 1) * 3 + (di + 1)) : ((di + 1) * 3 + (do_ + 1));
        const float* w = layer ? w2 : w1;
        g_wq[orient][layer][i] = make_float2(w[(2 * p) * 9 + off], w[(2 * p + 1) * 9 + off]);
    }
    if (tid < NP) g_b1q[tid] = make_float2(b1[2 * tid], b1[2 * tid + 1]);

    Top2 t;
    t.v1 = g_amp[tid]; t.i1 = tid; t.v2 = -1e30f; t.i2 = 0x7FFFFFFF;
    #pragma unroll
    for (int off = 16; off >= 1; off >>= 1) {
        Top2 o;
        o.v1 = __shfl_xor_sync(0xFFFFFFFFu, t.v1, off);
        o.i1 = __shfl_xor_sync(0xFFFFFFFFu, t.i1, off);
        o.v2 = __shfl_xor_sync(0xFFFFFFFFu, t.v2, off);
        o.i2 = __shfl_xor_sync(0xFFFFFFFFu, t.i2, off);
        t = t2merge(t, o);
    }
    if ((tid & 31) == 0) warpRes[tid >> 5] = t;
    __syncthreads();

    if (tid < 32) {
        t = warpRes[tid];
        #pragma unroll
        for (int off = 16; off >= 1; off >>= 1) {
            Top2 o;
            o.v1 = __shfl_xor_sync(0xFFFFFFFFu, t.v1, off);
            o.i1 = __shfl_xor_sync(0xFFFFFFFFu, t.i1, off);
            o.v2 = __shfl_xor_sync(0xFFFFFFFFu, t.v2, off);
            o.i2 = __shfl_xor_sync(0xFFFFFFFFu, t.i2, off);
            t = t2merge(t, o);
        }
        if (tid == 0) {
            float e2 = __expf(t.v2 - t.v1);
            float inv = 1.f / (1.f + e2);
            float wgts[2] = { inv, e2 * inv };
            int   idxs[2] = { t.i1, t.i2 };
            for (int tt = 0; tt < 2; tt++) {
                int f = idxs[tt] + 1;
                int P = (int)llrint((double)T_LEN / (double)f); if (P < 1) P = 1;
                int cols = (T_LEN + P - 1) / P;
                int orient = (P <= cols) ? 0 : 1;
                int inner = orient ? cols : P;
                int outer = orient ? P : cols;
                int S = inner + 2;
                PMeta pm;
                pm.S = S; pm.padL = outer * S;
                pm.inner = inner; pm.outer = outer;
                pm.stepO = orient ? 1 : P;
                pm.stepI = orient ? P : 1;
                pm.orient = orient;
                pm.magic = 0xFFFFFFFFu / (unsigned)S + 1u;
                pm.wgt = wgts[tt];
                g_pm[tt] = pm;
            }
        }
    }
}

__device__ __forceinline__ ull gelu2(ull vq, ull C0, ull C1, ull HALF) {
    ull v2q = mul2(vq, vq);
    ull uq  = mul2(vq, fma2(C1, v2q, C0));
    float ul, uh;
    unpack2(uq, ul, uh);
    float tl, th;
    asm("tanh.approx.f32 %0, %1;" : "=f"(tl) : "f"(ul));
    asm("tanh.approx.f32 %0, %1;" : "=f"(th) : "f"(uh));
    ull tq = pack2(tl, th);
    return mul2(vq, fma2(HALF, tq, HALF));
}

// ---------------------------------------------------------------------------
// 3) f32x2 channel-paired register-resident fused conv
// ---------------------------------------------------------------------------
__global__ __launch_bounds__(256, 2) void conv_kernel(
        const float* __restrict__ x,
        const float* __restrict__ b2) {
    const int period = blockIdx.z;
    const PMeta pm = g_pm[period];
    const int S = pm.S, inner = pm.inner, padL = pm.padL;
    const int stepO = pm.stepO, stepI = pm.stepI;
    const unsigned M = pm.magic;

    if (blockIdx.x * OUTSPAN >= padL) return;
    const int qb  = blockIdx.x * OUTSPAN - 48;
    const int b   = blockIdx.y;
    const int tid = threadIdx.x;

    __shared__ float xs[XLEN2];
    __shared__ float sUm[USPAN];
    __shared__ float sUp[USPAN];
    __shared__ __align__(16) ull w1s[(DMOD/2) * 9];
    __shared__ __align__(16) ull w2s[(DMOD/2) * 9];
    __shared__ ull b1s[DMOD / 2];
    __shared__ float b2s_s;

    {
        const ull* gw1 = (const ull*)g_wq[pm.orient][0];
        const ull* gw2 = (const ull*)g_wq[pm.orient][1];
        for (int i = tid; i < (DMOD/2) * 9; i += 256) {
            w1s[i] = gw1[i];
            w2s[i] = gw2[i];
        }
        if (tid < DMOD / 2) b1s[tid] = ((const ull*)g_b1q)[tid];
        if (tid == 0) b2s_s = b2[0];
    }

    const float* xb = x + (size_t)b * T_LEN;
    for (int i = tid; i < XLEN2; i += 256) {
        int q = qb - 52 + i;
        float v = 0.f;
        if (q >= 0 && q < padL) {
            unsigned o = mdiv((unsigned)q, M);
            int i_ = q - (int)o * S - 1;
            if (i_ >= 0 && i_ < inner) {
                int n = (int)o * stepO + i_ * stepI;
                if (n < T_LEN) v = xb[n];
            }
        }
        xs[i] = v;
    }
    __syncthreads();

    ull T0[8], T1[8], T2[8];
    {
        const float* xr = xs + tid * 4 + 50;
        #pragma unroll
        for (int k = 0; k < 8; k++) {
            T1[k] = bcast2(xr[k]);
            T2[k] = bcast2(xr[S + k]);
            T0[k] = bcast2(xr[-S + k]);
        }
    }

    float mf[6];
    #pragma unroll
    for (int t = 0; t < 6; t++) {
        int q = qb + tid * 4 - 1 + t;
        bool v = false;
        if (q >= 0 && q < padL) {
            unsigned o = mdiv((unsigned)q, M);
            int i_ = q - (int)o * S - 1;
            v = (i_ >= 0 && i_ < inner);
        }
        mf[t] = v ? 1.f : 0.f;
    }
    int on[4]; bool ov[4]; bool anyv = false;
    #pragma unroll
    for (int r = 0; r < 4; r++) {
        int lj = tid * 4 + r;
        int q  = qb + lj;
        ov[r] = false; on[r] = 0;
        if (lj >= 48 && lj < 48 + OUTSPAN && q < padL) {
            unsigned o = mdiv((unsigned)q, M);
            int i_ = q - (int)o * S - 1;
            if (i_ >= 0 && i_ < inner) {
                int n = (int)o * stepO + i_ * stepI;
                if (n < T_LEN) { ov[r] = true; on[r] = n; anyv = true; }
            }
        }
    }

    const ull C0   = bcast2(0.7978845608f);
    const ull C1   = bcast2(0.035677408136f);
    const ull HALF = bcast2(0.5f);

    ull U0q[4], Upq[4], Umq[4];
    #pragma unroll
    for (int r = 0; r < 4; r++) { U0q[r] = 0ull; Upq[r] = 0ull; Umq[r] = 0ull; }

    for (int pch = 0; pch < DMOD / 2; pch++) {
        const ull* w1r = &w1s[pch * 9];
        const ull* w2r = &w2s[pch * 9];
        ull bq = b1s[pch];
        ull hq[6];
        #pragma unroll
        for (int t = 0; t < 6; t++) {
            ull a = bq;
            a = fma2(w1r[0], T1[t],     a);
            a = fma2(w1r[1], T1[t + 1], a);
            a = fma2(w1r[2], T1[t + 2], a);
            a = fma2(w1r[3], T2[t],     a);
            a = fma2(w1r[4], T2[t + 1], a);
            a = fma2(w1r[5], T2[t + 2], a);
            a = fma2(w1r[6], T0[t],     a);
            a = fma2(w1r[7], T0[t + 1], a);
            a = fma2(w1r[8], T0[t + 2], a);
            hq[t] = mul2(gelu2(a, C0, C1, HALF), bcast2(mf[t]));
        }
        #pragma unroll
        for (int r = 0; r < 4; r++) {
            U0q[r] = fma2(w2r[0], hq[r],     U0q[r]);
            U0q[r] = fma2(w2r[1], hq[r + 1], U0q[r]);
            U0q[r] = fma2(w2r[2], hq[r + 2], U0q[r]);
            Upq[r] = fma2(w2r[3], hq[r],     Upq[r]);
            Upq[r] = fma2(w2r[4], hq[r + 1], Upq[r]);
            Upq[r] = fma2(w2r[5], hq[r + 2], Upq[r]);
            Umq[r] = fma2(w2r[6], hq[r],     Umq[r]);
            Umq[r] = fma2(w2r[7], hq[r + 1], Umq[r]);
            Umq[r] = fma2(w2r[8], hq[r + 2], Umq[r]);
        }
    }

    float U0[4], Um[4], Up[4];
    #pragma unroll
    for (int r = 0; r < 4; r++) {
        float lo, hi;
        unpack2(U0q[r], lo, hi); U0[r] = lo + hi;
        unpack2(Upq[r], lo, hi); Up[r] = lo + hi;
        unpack2(Umq[r], lo, hi); Um[r] = lo + hi;
    }
    *(float4*)(sUm + tid * 4) = make_float4(Um[0], Um[1], Um[2], Um[3]);
    *(float4*)(sUp + tid * 4) = make_float4(Up[0], Up[1], Up[2], Up[3]);
    __syncthreads();

    if (anyv) {
        float* yout = g_y2[period] + (size_t)b * T_LEN;
        #pragma unroll
        for (int r = 0; r < 4; r++) {
            if (ov[r]) {
                int lj = tid * 4 + r;
                float val = b2s_s + U0[r] + sUm[lj - S] + sUp[lj + S];
                yout[on[r]] = pm.wgt * val;
            }
        }
    }
}

// ---------------------------------------------------------------------------
// 4) Head GEMM, split-K=4, GBK=64, f32x2 inner
// ---------------------------------------------------------------------------
#define GBM 64
#define GBN 64
#define GBK 64
__global__ __launch_bounds__(256) void head_gemm_kernel(
        const float* __restrict__ hw) {
    __shared__ __align__(16) float As[GBK][GBM];
    __shared__ __align__(16) float Bs[GBK][GBN];
    const int tid = threadIdx.x;
    const int n0 = blockIdx.x * GBN, m0 = blockIdx.y * GBM;
    const int kz = blockIdx.z;
    const int ty = tid / 16, tx = tid % 16;
    const int tm = ty * 4, tn = tx * 4;

    const float* y0 = g_y2[0];
    const float* y1 = g_y2[1];

    ull acc2[4][2];
    #pragma unroll
    for (int i = 0; i < 4; i++) { acc2[i][0] = 0ull; acc2[i][1] = 0ull; }

    const int kbase = kz * KSEG;
    for (int k0 = kbase; k0 < kbase + KSEG; k0 += GBK) {
        #pragma unroll
        for (int i = tid; i < GBM * GBK; i += 256) {
            int m = i / GBK, k = i % GBK;
            size_t off = (size_t)(m0 + m) * T_LEN + k0 + k;
            As[k][m] = y0[off] + y1[off];
        }
        #pragma unroll
        for (int i = tid; i < GBN * GBK; i += 256) {
            int n = i / GBK, k = i % GBK;
            Bs[k][n] = (n0 + n < H_OUT) ? hw[(size_t)(n0 + n) * T_LEN + k0 + k] : 0.f;
        }
        __syncthreads();
        #pragma unroll
        for (int k = 0; k < GBK; k++) {
            float4 a4 = *(const float4*)&As[k][tm];
            float4 b4 = *(const float4*)&Bs[k][tn];
            ull bq0 = pack2(b4.x, b4.y);
            ull bq1 = pack2(b4.z, b4.w);
            float av[4] = {a4.x, a4.y, a4.z, a4.w};
            #pragma unroll
            for (int i = 0; i < 4; i++) {
                ull ai = bcast2(av[i]);
                acc2[i][0] = fma2(ai, bq0, acc2[i][0]);
                acc2[i][1] = fma2(ai, bq1, acc2[i][1]);
            }
        }
        __syncthreads();
    }
    float* outp = g_hp[kz];
    #pragma unroll
    for (int i = 0; i < 4; i++) {
        int m = m0 + tm + i;
        float v0, v1v, v2, v3;
        unpack2(acc2[i][0], v0, v1v);
        unpack2(acc2[i][1], v2, v3);
        float vals[4] = {v0, v1v, v2, v3};
        #pragma unroll
        for (int j = 0; j < 4; j++) {
            int n = n0 + tn + j;
            if (n < H_OUT) outp[(size_t)m * H_OUT + n] = vals[j];
        }
    }
}

__global__ void head_epilogue_kernel(const float* __restrict__ hb,
                                     float* __restrict__ out) {
    int idx4 = blockIdx.x * blockDim.x + threadIdx.x;
    if (idx4 >= NB * H_OUT / 4) return;
    int base = idx4 * 4;
    int n = base % H_OUT;
    float4 v = *(const float4*)&hb[n];
    #pragma unroll
    for (int kz = 0; kz < KSPLIT; kz++) {
        float4 p = *(const float4*)&g_hp[kz][base];
        v.x += p.x; v.y += p.y; v.z += p.z; v.w += p.w;
    }
    *(float4*)&out[base] = v;
}

// ---------------------------------------------------------------------------
extern "C" void kernel_launch(void* const* d_in, const int* in_sizes, int n_in,
                              void* d_out, int out_size) {
    const float* x  = (const float*)d_in[0];
    const float* w1 = (const float*)d_in[1];
    const float* b1 = (const float*)d_in[2];
    const float* w2 = (const float*)d_in[3];
    const float* b2 = (const float*)d_in[4];
    const float* hw = (const float*)d_in[5];
    const float* hb = (const float*)d_in[6];
    float* out = (float*)d_out;

    fft_kernel<<<NB, 512>>>(x);
    reduce_amp_kernel<<<NBINS / 256, 256>>>();
    prep_kernel<<<1, NBINS>>>(w1, w2, b1);
    conv_kernel<<<dim3(NCONVBLK, NB, 2), 256>>>(x, b2);
    head_gemm_kernel<<<dim3((H_OUT + GBN - 1) / GBN, NB / GBM, KSPLIT), 256>>>(hw);
    head_epilogue_kernel<<<(NB * H_OUT / 4 + 255) / 256, 256>>>(hb, out);
}